// round 2
// baseline (speedup 1.0000x reference)
#include <cuda_runtime.h>
#include <math.h>

#define T_TOTAL 131072
#define CDIM 256
#define MDIM 128
#define TILE 128

#define SA_STRIDE 129   // [k][x] transposed tiles
#define PS_STRIDE 129   // [r][m]
#define Q2_STRIDE 132   // [r][c], multiple of 4 for float4 stores

// region sizes in floats
#define REG_B 16512                 // 128*129
#define REG_A1 16896                // max(128*129, 128*132)  (phase1 A region)
#define REG_A2 32768                // 128*256 (phase2: full new_mem)
#define SMEM1_BYTES ((REG_B + REG_A1) * 4)   // 133632
#define SMEM2_BYTES ((REG_B + REG_A2) * 4)   // 197120

#define OUT_OFF   0
#define ATTN_OFF  ((size_t)T_TOTAL * 2 * CDIM)                 // 67108864
#define NM_OFF    (ATTN_OFF + (size_t)T_TOTAL * MDIM)          // 83886080

__device__ float g_add_mem[MDIM * CDIM];
__device__ float g_new_mem[MDIM * CDIM];

__global__ void zero_kernel() {
    int i = blockIdx.x * blockDim.x + threadIdx.x;
    if (i < MDIM * CDIM) g_add_mem[i] = 0.0f;
}

// ---------------------------------------------------------------------------
// Phase 1: per 128-row tile: S = Q@mem^T, softmax(+clamp 1e-8) -> P,
// then atomicAdd partial P^T@Q into g_add_mem.
// ---------------------------------------------------------------------------
__global__ void __launch_bounds__(256, 1)
phase1_kernel(const float* __restrict__ q, const float* __restrict__ mem) {
    extern __shared__ float sm[];
    float* B = sm;            // mem_s [k][m] (stride 129) -> later Ps [r][m]
    float* A = sm + REG_B;    // Qs [k][r] (stride 129) -> later Qs2 [r][c] (stride 132)

    const int tid = threadIdx.x;
    const int tr = tid >> 4;          // 0..15
    const int tc = tid & 15;          // 0..15
    const int row0 = blockIdx.x * TILE;

    float S[8][8];
#pragma unroll
    for (int i = 0; i < 8; i++)
#pragma unroll
        for (int j = 0; j < 8; j++) S[i][j] = 0.0f;

    // ---- Stage A: S accumulation over k in two 128-chunks ----
    for (int kc = 0; kc < 2; kc++) {
#pragma unroll
        for (int l = 0; l < 16; l++) {
            int e = l * 256 + tid;          // float4 index, 0..4095
            int r = e >> 5;
            int k4 = e & 31;
            float4 v = *(const float4*)(q + (size_t)(row0 + r) * CDIM + kc * 128 + k4 * 4);
            A[(4 * k4 + 0) * SA_STRIDE + r] = v.x;
            A[(4 * k4 + 1) * SA_STRIDE + r] = v.y;
            A[(4 * k4 + 2) * SA_STRIDE + r] = v.z;
            A[(4 * k4 + 3) * SA_STRIDE + r] = v.w;
        }
#pragma unroll
        for (int l = 0; l < 16; l++) {
            int e = l * 256 + tid;
            int m = e >> 5;
            int k4 = e & 31;
            float4 v = *(const float4*)(mem + (size_t)m * CDIM + kc * 128 + k4 * 4);
            B[(4 * k4 + 0) * SA_STRIDE + m] = v.x;
            B[(4 * k4 + 1) * SA_STRIDE + m] = v.y;
            B[(4 * k4 + 2) * SA_STRIDE + m] = v.z;
            B[(4 * k4 + 3) * SA_STRIDE + m] = v.w;
        }
        __syncthreads();
#pragma unroll 4
        for (int k = 0; k < 128; k++) {
            float a[8], b[8];
#pragma unroll
            for (int i = 0; i < 8; i++) a[i] = A[k * SA_STRIDE + tr + 16 * i];
#pragma unroll
            for (int j = 0; j < 8; j++) b[j] = B[k * SA_STRIDE + tc + 16 * j];
#pragma unroll
            for (int i = 0; i < 8; i++)
#pragma unroll
                for (int j = 0; j < 8; j++) S[i][j] = fmaf(a[i], b[j], S[i][j]);
        }
        __syncthreads();
    }

    // ---- Stage B: softmax over m (row = tr+16i owned by the 16 lanes sharing tr) ----
    float P[8][8];
#pragma unroll
    for (int i = 0; i < 8; i++) {
        float mx = -1e30f;
#pragma unroll
        for (int j = 0; j < 8; j++) mx = fmaxf(mx, S[i][j]);
#pragma unroll
        for (int o = 8; o >= 1; o >>= 1) mx = fmaxf(mx, __shfl_xor_sync(0xffffffffu, mx, o));
        float sum = 0.0f;
#pragma unroll
        for (int j = 0; j < 8; j++) { P[i][j] = __expf(S[i][j] - mx); sum += P[i][j]; }
#pragma unroll
        for (int o = 8; o >= 1; o >>= 1) sum += __shfl_xor_sync(0xffffffffu, sum, o);
        float inv = 1.0f / sum;
#pragma unroll
        for (int j = 0; j < 8; j++) P[i][j] = fmaxf(P[i][j] * inv, 1e-8f);
    }
    // write P to smem (Ps[r][m])
#pragma unroll
    for (int i = 0; i < 8; i++)
#pragma unroll
        for (int j = 0; j < 8; j++)
            B[(tr + 16 * i) * PS_STRIDE + tc + 16 * j] = P[i][j];
    __syncthreads();

    // ---- Stage C: add_mem_partial[m][c] = sum_r P[r][m]*Q[r][c], atomicAdd ----
    for (int cc = 0; cc < 2; cc++) {
#pragma unroll
        for (int l = 0; l < 16; l++) {
            int e = l * 256 + tid;
            int r = e >> 5;
            int c4 = e & 31;
            float4 v = *(const float4*)(q + (size_t)(row0 + r) * CDIM + cc * 128 + c4 * 4);
            *(float4*)(A + r * Q2_STRIDE + c4 * 4) = v;
        }
        __syncthreads();
        float acc[8][8];
#pragma unroll
        for (int i = 0; i < 8; i++)
#pragma unroll
            for (int j = 0; j < 8; j++) acc[i][j] = 0.0f;
#pragma unroll 4
        for (int r = 0; r < 128; r++) {
            float p[8], qq[8];
#pragma unroll
            for (int i = 0; i < 8; i++) p[i] = B[r * PS_STRIDE + tr + 16 * i];
#pragma unroll
            for (int j = 0; j < 8; j++) qq[j] = A[r * Q2_STRIDE + tc + 16 * j];
#pragma unroll
            for (int i = 0; i < 8; i++)
#pragma unroll
                for (int j = 0; j < 8; j++) acc[i][j] = fmaf(p[i], qq[j], acc[i][j]);
        }
#pragma unroll
        for (int i = 0; i < 8; i++)
#pragma unroll
            for (int j = 0; j < 8; j++)
                atomicAdd(&g_add_mem[(tr + 16 * i) * CDIM + cc * 128 + tc + 16 * j], acc[i][j]);
        __syncthreads();
    }
}

// ---------------------------------------------------------------------------
// Gate + memory update + row L2-normalize (tiny)
// ---------------------------------------------------------------------------
__global__ void __launch_bounds__(256)
gate_kernel(const float* __restrict__ mem,
            const float* __restrict__ U_w, const float* __restrict__ U_b,
            const float* __restrict__ W_w, const float* __restrict__ W_b,
            float* __restrict__ out_nm) {
    __shared__ float mrow[CDIM];
    __shared__ float arow[CDIM];
    __shared__ float red[256];
    const int m = blockIdx.x;
    const int c = threadIdx.x;

    mrow[c] = mem[(size_t)m * CDIM + c];
    arow[c] = g_add_mem[(size_t)m * CDIM + c];
    __syncthreads();

    float acc = U_b[c] + W_b[c];
    const float* uw = U_w + (size_t)c * CDIM;
    const float* ww = W_w + (size_t)c * CDIM;
#pragma unroll 8
    for (int k = 0; k < CDIM; k++) acc = fmaf(mrow[k], uw[k], fmaf(arow[k], ww[k], acc));

    float gate = 1.0f / (1.0f + __expf(-acc));
    float mv = mrow[c], av = arow[c];
    float nm = 0.9f * mv + 0.1f * ((1.0f - gate) * mv + gate * av);

    red[c] = nm * nm;
    __syncthreads();
    for (int s = 128; s > 0; s >>= 1) {
        if (c < s) red[c] += red[c + s];
        __syncthreads();
    }
    float norm = sqrtf(red[0]);
    float inv = 1.0f / fmaxf(norm, 1e-12f);
    float v = nm * inv;
    g_new_mem[(size_t)m * CDIM + c] = v;
    out_nm[(size_t)m * CDIM + c] = v;
}

// ---------------------------------------------------------------------------
// Phase 2: S = Q@new_mem^T, softmax -> hard_shrink_relu -> L1 norm -> attn,
// add_memory = attn@new_mem; also copies q into out[:, :256].
// ---------------------------------------------------------------------------
__global__ void __launch_bounds__(256, 1)
phase2_kernel(const float* __restrict__ q, float* __restrict__ out,
              float* __restrict__ attn_out) {
    extern __shared__ float sm[];
    float* B = sm;            // nm chunk [k][m] -> later Ps [r][m]
    float* A = sm + REG_B;    // Qs [k][r] -> later full new_mem [m][c] (stride 256)

    const int tid = threadIdx.x;
    const int tr = tid >> 4;
    const int tc = tid & 15;
    const int row0 = blockIdx.x * TILE;

    float S[8][8];
#pragma unroll
    for (int i = 0; i < 8; i++)
#pragma unroll
        for (int j = 0; j < 8; j++) S[i][j] = 0.0f;

    for (int kc = 0; kc < 2; kc++) {
#pragma unroll
        for (int l = 0; l < 16; l++) {
            int e = l * 256 + tid;
            int r = e >> 5;
            int k4 = e & 31;
            float4 v = *(const float4*)(q + (size_t)(row0 + r) * CDIM + kc * 128 + k4 * 4);
            A[(4 * k4 + 0) * SA_STRIDE + r] = v.x;
            A[(4 * k4 + 1) * SA_STRIDE + r] = v.y;
            A[(4 * k4 + 2) * SA_STRIDE + r] = v.z;
            A[(4 * k4 + 3) * SA_STRIDE + r] = v.w;
            // free q-copy into out[:, 0:256]
            *(float4*)(out + (size_t)(row0 + r) * (2 * CDIM) + kc * 128 + k4 * 4) = v;
        }
#pragma unroll
        for (int l = 0; l < 16; l++) {
            int e = l * 256 + tid;
            int m = e >> 5;
            int k4 = e & 31;
            float4 v = *(const float4*)(g_new_mem + (size_t)m * CDIM + kc * 128 + k4 * 4);
            B[(4 * k4 + 0) * SA_STRIDE + m] = v.x;
            B[(4 * k4 + 1) * SA_STRIDE + m] = v.y;
            B[(4 * k4 + 2) * SA_STRIDE + m] = v.z;
            B[(4 * k4 + 3) * SA_STRIDE + m] = v.w;
        }
        __syncthreads();
#pragma unroll 4
        for (int k = 0; k < 128; k++) {
            float a[8], b[8];
#pragma unroll
            for (int i = 0; i < 8; i++) a[i] = A[k * SA_STRIDE + tr + 16 * i];
#pragma unroll
            for (int j = 0; j < 8; j++) b[j] = B[k * SA_STRIDE + tc + 16 * j];
#pragma unroll
            for (int i = 0; i < 8; i++)
#pragma unroll
                for (int j = 0; j < 8; j++) S[i][j] = fmaf(a[i], b[j], S[i][j]);
        }
        __syncthreads();
    }

    // softmax -> hard_shrink_relu -> L1 normalize
    float P[8][8];
#pragma unroll
    for (int i = 0; i < 8; i++) {
        float mx = -1e30f;
#pragma unroll
        for (int j = 0; j < 8; j++) mx = fmaxf(mx, S[i][j]);
#pragma unroll
        for (int o = 8; o >= 1; o >>= 1) mx = fmaxf(mx, __shfl_xor_sync(0xffffffffu, mx, o));
        float sum = 0.0f;
#pragma unroll
        for (int j = 0; j < 8; j++) { P[i][j] = __expf(S[i][j] - mx); sum += P[i][j]; }
#pragma unroll
        for (int o = 8; o >= 1; o >>= 1) sum += __shfl_xor_sync(0xffffffffu, sum, o);
        float inv = 1.0f / sum;
        float l1 = 0.0f;
#pragma unroll
        for (int j = 0; j < 8; j++) {
            float a = P[i][j] * inv;
            float d = a - 0.0025f;
            float a2 = fmaxf(d, 0.0f) * a / (fabsf(d) + 1e-12f);
            P[i][j] = a2;
            l1 += a2;  // a2 >= 0
        }
#pragma unroll
        for (int o = 8; o >= 1; o >>= 1) l1 += __shfl_xor_sync(0xffffffffu, l1, o);
        float invl = 1.0f / fmaxf(l1, 1e-12f);
#pragma unroll
        for (int j = 0; j < 8; j++) P[i][j] *= invl;
    }
    // write attn to gmem + Ps to smem
#pragma unroll
    for (int i = 0; i < 8; i++) {
        int r = tr + 16 * i;
#pragma unroll
        for (int j = 0; j < 8; j++) {
            int m = tc + 16 * j;
            B[r * PS_STRIDE + m] = P[i][j];
            attn_out[(size_t)(row0 + r) * MDIM + m] = P[i][j];
        }
    }
    __syncthreads();

    // load full new_mem [m][c] into A (stride 256)
#pragma unroll
    for (int l = 0; l < 32; l++) {
        int e = l * 256 + tid;  // float4 index, 0..8191
        int mm = e >> 6;
        int c4 = e & 63;
        *(float4*)(A + mm * 256 + c4 * 4) = *(const float4*)(g_new_mem + (size_t)mm * 256 + c4 * 4);
    }
    __syncthreads();

    // add_memory[r][c] = sum_m P[r][m] * nm[m][c]
    for (int cc = 0; cc < 2; cc++) {
        float acc[8][8];
#pragma unroll
        for (int i = 0; i < 8; i++)
#pragma unroll
            for (int j = 0; j < 8; j++) acc[i][j] = 0.0f;
#pragma unroll 4
        for (int m = 0; m < 128; m++) {
            float p[8], b[8];
#pragma unroll
            for (int i = 0; i < 8; i++) p[i] = B[(tr + 16 * i) * PS_STRIDE + m];
#pragma unroll
            for (int j = 0; j < 8; j++) b[j] = A[m * 256 + cc * 128 + tc + 16 * j];
#pragma unroll
            for (int i = 0; i < 8; i++)
#pragma unroll
                for (int j = 0; j < 8; j++) acc[i][j] = fmaf(p[i], b[j], acc[i][j]);
        }
#pragma unroll
        for (int i = 0; i < 8; i++) {
            int r = row0 + tr + 16 * i;
#pragma unroll
            for (int j = 0; j < 8; j++) {
                int c = cc * 128 + tc + 16 * j;
                out[(size_t)r * (2 * CDIM) + CDIM + c] = acc[i][j];
            }
        }
    }
}

// ---------------------------------------------------------------------------
extern "C" void kernel_launch(void* const* d_in, const int* in_sizes, int n_in,
                              void* d_out, int out_size) {
    const float* q   = (const float*)d_in[0];
    const float* mem = (const float*)d_in[1];
    const float* U_w = (const float*)d_in[2];
    const float* U_b = (const float*)d_in[3];
    const float* W_w = (const float*)d_in[4];
    const float* W_b = (const float*)d_in[5];
    float* out = (float*)d_out;
    float* attn_out = out + ATTN_OFF;
    float* nm_out = out + NM_OFF;

    cudaFuncSetAttribute(phase1_kernel, cudaFuncAttributeMaxDynamicSharedMemorySize, SMEM1_BYTES);
    cudaFuncSetAttribute(phase2_kernel, cudaFuncAttributeMaxDynamicSharedMemorySize, SMEM2_BYTES);

    zero_kernel<<<(MDIM * CDIM + 255) / 256, 256>>>();
    phase1_kernel<<<T_TOTAL / TILE, 256, SMEM1_BYTES>>>(q, mem);
    gate_kernel<<<MDIM, 256>>>(mem, U_w, U_b, W_w, W_b, nm_out);
    phase2_kernel<<<T_TOTAL / TILE, 256, SMEM2_BYTES>>>(q, out, attn_out);
}

// round 3
// speedup vs baseline: 1.0012x; 1.0012x over previous
#include <cuda_runtime.h>
#include <math.h>

#define T_TOTAL 131072
#define CDIM 256
#define MDIM 128
#define TILE 128

#define SA_STRIDE 129   // [k][x] transposed tiles
#define PS_STRIDE 129   // [r][m]
#define Q2_STRIDE 132   // [r][c], multiple of 4 for float4 stores

// region sizes in floats
#define REG_B 16512                 // 128*129
#define REG_A1 16896                // max(128*129, 128*132)  (phase1 A region)
#define REG_A2 32768                // 128*256 (phase2: full new_mem)
#define SMEM1_BYTES ((REG_B + REG_A1) * 4)   // 133632
#define SMEM2_BYTES ((REG_B + REG_A2) * 4)   // 197120

#define OUT_OFF   0
#define ATTN_OFF  ((size_t)T_TOTAL * 2 * CDIM)                 // 67108864
#define NM_OFF    (ATTN_OFF + (size_t)T_TOTAL * MDIM)          // 83886080

__device__ float g_add_mem[MDIM * CDIM];
__device__ float g_new_mem[MDIM * CDIM];

__global__ void zero_kernel() {
    int i = blockIdx.x * blockDim.x + threadIdx.x;
    if (i < MDIM * CDIM) g_add_mem[i] = 0.0f;
}

// ---------------------------------------------------------------------------
// Phase 1: per 128-row tile: S = Q@mem^T, softmax(+clamp 1e-8) -> P,
// then atomicAdd partial P^T@Q into g_add_mem.
// ---------------------------------------------------------------------------
__global__ void __launch_bounds__(256, 1)
phase1_kernel(const float* __restrict__ q, const float* __restrict__ mem) {
    extern __shared__ float sm[];
    float* B = sm;            // mem_s [k][m] (stride 129) -> later Ps [r][m]
    float* A = sm + REG_B;    // Qs [k][r] (stride 129) -> later Qs2 [r][c] (stride 132)

    const int tid = threadIdx.x;
    const int tr = tid >> 4;          // 0..15
    const int tc = tid & 15;          // 0..15
    const int row0 = blockIdx.x * TILE;

    float S[8][8];
#pragma unroll
    for (int i = 0; i < 8; i++)
#pragma unroll
        for (int j = 0; j < 8; j++) S[i][j] = 0.0f;

    // ---- Stage A: S accumulation over k in two 128-chunks ----
    for (int kc = 0; kc < 2; kc++) {
#pragma unroll
        for (int l = 0; l < 16; l++) {
            int e = l * 256 + tid;          // float4 index, 0..4095
            int r = e >> 5;
            int k4 = e & 31;
            float4 v = *(const float4*)(q + (size_t)(row0 + r) * CDIM + kc * 128 + k4 * 4);
            A[(4 * k4 + 0) * SA_STRIDE + r] = v.x;
            A[(4 * k4 + 1) * SA_STRIDE + r] = v.y;
            A[(4 * k4 + 2) * SA_STRIDE + r] = v.z;
            A[(4 * k4 + 3) * SA_STRIDE + r] = v.w;
        }
#pragma unroll
        for (int l = 0; l < 16; l++) {
            int e = l * 256 + tid;
            int m = e >> 5;
            int k4 = e & 31;
            float4 v = *(const float4*)(mem + (size_t)m * CDIM + kc * 128 + k4 * 4);
            B[(4 * k4 + 0) * SA_STRIDE + m] = v.x;
            B[(4 * k4 + 1) * SA_STRIDE + m] = v.y;
            B[(4 * k4 + 2) * SA_STRIDE + m] = v.z;
            B[(4 * k4 + 3) * SA_STRIDE + m] = v.w;
        }
        __syncthreads();
#pragma unroll 4
        for (int k = 0; k < 128; k++) {
            float a[8], b[8];
#pragma unroll
            for (int i = 0; i < 8; i++) a[i] = A[k * SA_STRIDE + tr + 16 * i];
#pragma unroll
            for (int j = 0; j < 8; j++) b[j] = B[k * SA_STRIDE + tc + 16 * j];
#pragma unroll
            for (int i = 0; i < 8; i++)
#pragma unroll
                for (int j = 0; j < 8; j++) S[i][j] = fmaf(a[i], b[j], S[i][j]);
        }
        __syncthreads();
    }

    // ---- Stage B: softmax over m (row = tr+16i owned by the 16 lanes sharing tr) ----
    float P[8][8];
#pragma unroll
    for (int i = 0; i < 8; i++) {
        float mx = -1e30f;
#pragma unroll
        for (int j = 0; j < 8; j++) mx = fmaxf(mx, S[i][j]);
#pragma unroll
        for (int o = 8; o >= 1; o >>= 1) mx = fmaxf(mx, __shfl_xor_sync(0xffffffffu, mx, o));
        float sum = 0.0f;
#pragma unroll
        for (int j = 0; j < 8; j++) { P[i][j] = __expf(S[i][j] - mx); sum += P[i][j]; }
#pragma unroll
        for (int o = 8; o >= 1; o >>= 1) sum += __shfl_xor_sync(0xffffffffu, sum, o);
        float inv = 1.0f / sum;
#pragma unroll
        for (int j = 0; j < 8; j++) P[i][j] = fmaxf(P[i][j] * inv, 1e-8f);
    }
    // write P to smem (Ps[r][m])
#pragma unroll
    for (int i = 0; i < 8; i++)
#pragma unroll
        for (int j = 0; j < 8; j++)
            B[(tr + 16 * i) * PS_STRIDE + tc + 16 * j] = P[i][j];
    __syncthreads();

    // ---- Stage C: add_mem_partial[m][c] = sum_r P[r][m]*Q[r][c], atomicAdd ----
    for (int cc = 0; cc < 2; cc++) {
#pragma unroll
        for (int l = 0; l < 16; l++) {
            int e = l * 256 + tid;
            int r = e >> 5;
            int c4 = e & 31;
            float4 v = *(const float4*)(q + (size_t)(row0 + r) * CDIM + cc * 128 + c4 * 4);
            *(float4*)(A + r * Q2_STRIDE + c4 * 4) = v;
        }
        __syncthreads();
        float acc[8][8];
#pragma unroll
        for (int i = 0; i < 8; i++)
#pragma unroll
            for (int j = 0; j < 8; j++) acc[i][j] = 0.0f;
#pragma unroll 4
        for (int r = 0; r < 128; r++) {
            float p[8], qq[8];
#pragma unroll
            for (int i = 0; i < 8; i++) p[i] = B[r * PS_STRIDE + tr + 16 * i];
#pragma unroll
            for (int j = 0; j < 8; j++) qq[j] = A[r * Q2_STRIDE + tc + 16 * j];
#pragma unroll
            for (int i = 0; i < 8; i++)
#pragma unroll
                for (int j = 0; j < 8; j++) acc[i][j] = fmaf(p[i], qq[j], acc[i][j]);
        }
#pragma unroll
        for (int i = 0; i < 8; i++)
#pragma unroll
            for (int j = 0; j < 8; j++)
                atomicAdd(&g_add_mem[(tr + 16 * i) * CDIM + cc * 128 + tc + 16 * j], acc[i][j]);
        __syncthreads();
    }
}

// ---------------------------------------------------------------------------
// Gate + memory update + row L2-normalize (tiny)
// ---------------------------------------------------------------------------
__global__ void __launch_bounds__(256)
gate_kernel(const float* __restrict__ mem,
            const float* __restrict__ U_w, const float* __restrict__ U_b,
            const float* __restrict__ W_w, const float* __restrict__ W_b,
            float* __restrict__ out_nm) {
    __shared__ float mrow[CDIM];
    __shared__ float arow[CDIM];
    __shared__ float red[256];
    const int m = blockIdx.x;
    const int c = threadIdx.x;

    mrow[c] = mem[(size_t)m * CDIM + c];
    arow[c] = g_add_mem[(size_t)m * CDIM + c];
    __syncthreads();

    float acc = U_b[c] + W_b[c];
    const float* uw = U_w + (size_t)c * CDIM;
    const float* ww = W_w + (size_t)c * CDIM;
#pragma unroll 8
    for (int k = 0; k < CDIM; k++) acc = fmaf(mrow[k], uw[k], fmaf(arow[k], ww[k], acc));

    float gate = 1.0f / (1.0f + __expf(-acc));
    float mv = mrow[c], av = arow[c];
    float nm = 0.9f * mv + 0.1f * ((1.0f - gate) * mv + gate * av);

    red[c] = nm * nm;
    __syncthreads();
    for (int s = 128; s > 0; s >>= 1) {
        if (c < s) red[c] += red[c + s];
        __syncthreads();
    }
    float norm = sqrtf(red[0]);
    float inv = 1.0f / fmaxf(norm, 1e-12f);
    float v = nm * inv;
    g_new_mem[(size_t)m * CDIM + c] = v;
    out_nm[(size_t)m * CDIM + c] = v;
}

// ---------------------------------------------------------------------------
// Phase 2: S = Q@new_mem^T, softmax -> hard_shrink_relu -> L1 norm -> attn,
// add_memory = attn@new_mem; also copies q into out[:, :256].
// ---------------------------------------------------------------------------
__global__ void __launch_bounds__(256, 1)
phase2_kernel(const float* __restrict__ q, float* __restrict__ out,
              float* __restrict__ attn_out) {
    extern __shared__ float sm[];
    float* B = sm;            // nm chunk [k][m] -> later Ps [r][m]
    float* A = sm + REG_B;    // Qs [k][r] -> later full new_mem [m][c] (stride 256)

    const int tid = threadIdx.x;
    const int tr = tid >> 4;
    const int tc = tid & 15;
    const int row0 = blockIdx.x * TILE;

    float S[8][8];
#pragma unroll
    for (int i = 0; i < 8; i++)
#pragma unroll
        for (int j = 0; j < 8; j++) S[i][j] = 0.0f;

    for (int kc = 0; kc < 2; kc++) {
#pragma unroll
        for (int l = 0; l < 16; l++) {
            int e = l * 256 + tid;
            int r = e >> 5;
            int k4 = e & 31;
            float4 v = *(const float4*)(q + (size_t)(row0 + r) * CDIM + kc * 128 + k4 * 4);
            A[(4 * k4 + 0) * SA_STRIDE + r] = v.x;
            A[(4 * k4 + 1) * SA_STRIDE + r] = v.y;
            A[(4 * k4 + 2) * SA_STRIDE + r] = v.z;
            A[(4 * k4 + 3) * SA_STRIDE + r] = v.w;
            // free q-copy into out[:, 0:256]
            *(float4*)(out + (size_t)(row0 + r) * (2 * CDIM) + kc * 128 + k4 * 4) = v;
        }
#pragma unroll
        for (int l = 0; l < 16; l++) {
            int e = l * 256 + tid;
            int m = e >> 5;
            int k4 = e & 31;
            float4 v = *(const float4*)(g_new_mem + (size_t)m * CDIM + kc * 128 + k4 * 4);
            B[(4 * k4 + 0) * SA_STRIDE + m] = v.x;
            B[(4 * k4 + 1) * SA_STRIDE + m] = v.y;
            B[(4 * k4 + 2) * SA_STRIDE + m] = v.z;
            B[(4 * k4 + 3) * SA_STRIDE + m] = v.w;
        }
        __syncthreads();
#pragma unroll 4
        for (int k = 0; k < 128; k++) {
            float a[8], b[8];
#pragma unroll
            for (int i = 0; i < 8; i++) a[i] = A[k * SA_STRIDE + tr + 16 * i];
#pragma unroll
            for (int j = 0; j < 8; j++) b[j] = B[k * SA_STRIDE + tc + 16 * j];
#pragma unroll
            for (int i = 0; i < 8; i++)
#pragma unroll
                for (int j = 0; j < 8; j++) S[i][j] = fmaf(a[i], b[j], S[i][j]);
        }
        __syncthreads();
    }

    // softmax -> hard_shrink_relu -> L1 normalize
    float P[8][8];
#pragma unroll
    for (int i = 0; i < 8; i++) {
        float mx = -1e30f;
#pragma unroll
        for (int j = 0; j < 8; j++) mx = fmaxf(mx, S[i][j]);
#pragma unroll
        for (int o = 8; o >= 1; o >>= 1) mx = fmaxf(mx, __shfl_xor_sync(0xffffffffu, mx, o));
        float sum = 0.0f;
#pragma unroll
        for (int j = 0; j < 8; j++) { P[i][j] = __expf(S[i][j] - mx); sum += P[i][j]; }
#pragma unroll
        for (int o = 8; o >= 1; o >>= 1) sum += __shfl_xor_sync(0xffffffffu, sum, o);
        float inv = 1.0f / sum;
        float l1 = 0.0f;
#pragma unroll
        for (int j = 0; j < 8; j++) {
            float a = P[i][j] * inv;
            float d = a - 0.0025f;
            float a2 = fmaxf(d, 0.0f) * a / (fabsf(d) + 1e-12f);
            P[i][j] = a2;
            l1 += a2;  // a2 >= 0
        }
#pragma unroll
        for (int o = 8; o >= 1; o >>= 1) l1 += __shfl_xor_sync(0xffffffffu, l1, o);
        float invl = 1.0f / fmaxf(l1, 1e-12f);
#pragma unroll
        for (int j = 0; j < 8; j++) P[i][j] *= invl;
    }
    // write attn to gmem + Ps to smem
#pragma unroll
    for (int i = 0; i < 8; i++) {
        int r = tr + 16 * i;
#pragma unroll
        for (int j = 0; j < 8; j++) {
            int m = tc + 16 * j;
            B[r * PS_STRIDE + m] = P[i][j];
            attn_out[(size_t)(row0 + r) * MDIM + m] = P[i][j];
        }
    }
    __syncthreads();

    // load full new_mem [m][c] into A (stride 256)
#pragma unroll
    for (int l = 0; l < 32; l++) {
        int e = l * 256 + tid;  // float4 index, 0..8191
        int mm = e >> 6;
        int c4 = e & 63;
        *(float4*)(A + mm * 256 + c4 * 4) = *(const float4*)(g_new_mem + (size_t)mm * 256 + c4 * 4);
    }
    __syncthreads();

    // add_memory[r][c] = sum_m P[r][m] * nm[m][c]
    for (int cc = 0; cc < 2; cc++) {
        float acc[8][8];
#pragma unroll
        for (int i = 0; i < 8; i++)
#pragma unroll
            for (int j = 0; j < 8; j++) acc[i][j] = 0.0f;
#pragma unroll 4
        for (int m = 0; m < 128; m++) {
            float p[8], b[8];
#pragma unroll
            for (int i = 0; i < 8; i++) p[i] = B[(tr + 16 * i) * PS_STRIDE + m];
#pragma unroll
            for (int j = 0; j < 8; j++) b[j] = A[m * 256 + cc * 128 + tc + 16 * j];
#pragma unroll
            for (int i = 0; i < 8; i++)
#pragma unroll
                for (int j = 0; j < 8; j++) acc[i][j] = fmaf(p[i], b[j], acc[i][j]);
        }
#pragma unroll
        for (int i = 0; i < 8; i++) {
            int r = row0 + tr + 16 * i;
#pragma unroll
            for (int j = 0; j < 8; j++) {
                int c = cc * 128 + tc + 16 * j;
                out[(size_t)r * (2 * CDIM) + CDIM + c] = acc[i][j];
            }
        }
    }
}

// ---------------------------------------------------------------------------
extern "C" void kernel_launch(void* const* d_in, const int* in_sizes, int n_in,
                              void* d_out, int out_size) {
    const float* q   = (const float*)d_in[0];
    const float* mem = (const float*)d_in[1];
    const float* U_w = (const float*)d_in[2];
    const float* U_b = (const float*)d_in[3];
    const float* W_w = (const float*)d_in[4];
    const float* W_b = (const float*)d_in[5];
    float* out = (float*)d_out;
    float* attn_out = out + ATTN_OFF;
    float* nm_out = out + NM_OFF;

    cudaFuncSetAttribute(phase1_kernel, cudaFuncAttributeMaxDynamicSharedMemorySize, SMEM1_BYTES);
    cudaFuncSetAttribute(phase2_kernel, cudaFuncAttributeMaxDynamicSharedMemorySize, SMEM2_BYTES);

    zero_kernel<<<(MDIM * CDIM + 255) / 256, 256>>>();
    phase1_kernel<<<T_TOTAL / TILE, 256, SMEM1_BYTES>>>(q, mem);
    gate_kernel<<<MDIM, 256>>>(mem, U_w, U_b, W_w, W_b, nm_out);
    phase2_kernel<<<T_TOTAL / TILE, 256, SMEM2_BYTES>>>(q, out, attn_out);
}

// round 5
// speedup vs baseline: 1.8125x; 1.8102x over previous
#include <cuda_runtime.h>
#include <cuda_bf16.h>
#include <cstdint>

#define TT 131072
#define CD 256
#define MD 128
#define NB 1024
#define ATTN_OFF ((size_t)TT*2*CD)
#define NM_OFF (ATTN_OFF+(size_t)TT*MD)

// smem byte offsets (dynamic)
#define QH 0
#define QL 34816
#define MH 69632
#define ML 104448
#define SOFF 0            // S fp32 [128][133] overwrites QH/QL
#define PH 69632          // P hi overwrites MH
#define PL 104448
#define BOUNCE 139264     // phase2 D2 bounce [128][132] fp32
#define SMEMB (139264 + 67584)
#define TS 136            // bf16 tile row stride (elements), 272B
#define SS 133            // S fp32 row stride

__device__ float g_add_mem[MD*CD];
__device__ __nv_bfloat16 g_nm_h[MD*CD], g_nm_l[MD*CD];

__device__ __forceinline__ uint32_t smem_u32(const void* p) {
    uint32_t a;
    asm("{ .reg .u64 t; cvta.to.shared.u64 t, %1; cvt.u32.u64 %0, t; }" : "=r"(a) : "l"(p));
    return a;
}
#define LDM4(r, a) asm volatile("ldmatrix.sync.aligned.m8n8.x4.shared.b16 {%0,%1,%2,%3}, [%4];" \
    : "=r"((r)[0]),"=r"((r)[1]),"=r"((r)[2]),"=r"((r)[3]) : "r"(a))
#define LDM4T(r, a) asm volatile("ldmatrix.sync.aligned.m8n8.x4.trans.shared.b16 {%0,%1,%2,%3}, [%4];" \
    : "=r"((r)[0]),"=r"((r)[1]),"=r"((r)[2]),"=r"((r)[3]) : "r"(a))
#define MMA(d, a, b0, b1) asm volatile( \
    "mma.sync.aligned.m16n8k16.row.col.f32.bf16.bf16.f32 {%0,%1,%2,%3}, {%4,%5,%6,%7}, {%8,%9}, {%0,%1,%2,%3};" \
    : "+f"((d)[0]),"+f"((d)[1]),"+f"((d)[2]),"+f"((d)[3]) \
    : "r"((a)[0]),"r"((a)[1]),"r"((a)[2]),"r"((a)[3]), "r"(b0),"r"(b1))

__device__ __forceinline__ uint32_t pk(__nv_bfloat16 a, __nv_bfloat16 b) {
    return (uint32_t)__bfloat16_as_ushort(a) | ((uint32_t)__bfloat16_as_ushort(b) << 16);
}
__device__ __forceinline__ float bl(uint32_t u) { return __bfloat162float(__ushort_as_bfloat16((unsigned short)u)); }
__device__ __forceinline__ float bh(uint32_t u) { return __bfloat162float(__ushort_as_bfloat16((unsigned short)(u >> 16))); }

// 128x128 fp32 chunk (row stride CD) -> hi/lo bf16 tiles at dh/dl (stride TS)
__device__ __forceinline__ void ldf(const float* __restrict__ src, char* sm, int dh, int dl,
                                    int tid, float* ocopy) {
#pragma unroll
    for (int i = 0; i < 16; i++) {
        int e = tid + i * 256, r = e >> 5, c4 = e & 31;
        float4 v = *(const float4*)(src + (size_t)r * CD + c4 * 4);
        if (ocopy) *(float4*)(ocopy + (size_t)r * 512 + c4 * 4) = v;
        __nv_bfloat16 h0 = __float2bfloat16(v.x), h1 = __float2bfloat16(v.y);
        __nv_bfloat16 h2 = __float2bfloat16(v.z), h3 = __float2bfloat16(v.w);
        uint32_t o = r * 272 + c4 * 8;
        *(uint2*)(sm + dh + o) = make_uint2(pk(h0, h1), pk(h2, h3));
        *(uint2*)(sm + dl + o) = make_uint2(
            pk(__float2bfloat16(v.x - __bfloat162float(h0)), __float2bfloat16(v.y - __bfloat162float(h1))),
            pk(__float2bfloat16(v.z - __bfloat162float(h2)), __float2bfloat16(v.w - __bfloat162float(h3))));
    }
}
// 128x128 bf16 hi/lo (row stride CD) -> tiles
__device__ __forceinline__ void ldb(const __nv_bfloat16* __restrict__ sh, const __nv_bfloat16* __restrict__ sl,
                                    char* sm, int dh, int dl, int tid) {
#pragma unroll
    for (int i = 0; i < 16; i++) {
        int e = tid + i * 256, r = e >> 5, c4 = e & 31;
        uint32_t o = r * 272 + c4 * 8;
        *(uint2*)(sm + dh + o) = *(const uint2*)(sh + (size_t)r * CD + c4 * 4);
        *(uint2*)(sm + dl + o) = *(const uint2*)(sl + (size_t)r * CD + c4 * 4);
    }
}

// one 128x128 MMA stage: d += A(stride TS at ah/al, rows aoff) x B(K-major rows boff)
// A non-trans from [m][k] tiles; B non-trans from [n][k] tiles. 3 passes hi/lo.
__device__ __forceinline__ void gemm_nn(float d[2][8][4], uint32_t smb, int ah, int al, int bh_, int bl_,
                                        int wm, int wn, int lane) {
    const int ar = (lane & 15), ak = (lane >> 4) * 8;
    const int br = (lane & 7) + ((lane >> 4) & 1) * 8, bk = ((lane >> 3) & 1) * 8;
#pragma unroll
    for (int ks = 0; ks < 8; ks++) {
        int k0 = ks * 16;
        uint32_t Ah[2][4], Al[2][4], Bh[4][4], Bl[4][4];
#pragma unroll
        for (int ms = 0; ms < 2; ms++) {
            uint32_t o = smb + (uint32_t)((wm * 32 + ms * 16 + ar) * 272 + (k0 + ak) * 2);
            LDM4(Ah[ms], o + ah); LDM4(Al[ms], o + al);
        }
#pragma unroll
        for (int nq = 0; nq < 4; nq++) {
            uint32_t o = smb + (uint32_t)((wn * 64 + nq * 16 + br) * 272 + (k0 + bk) * 2);
            LDM4(Bh[nq], o + bh_); LDM4(Bl[nq], o + bl_);
        }
#pragma unroll
        for (int ms = 0; ms < 2; ms++)
#pragma unroll
            for (int nq = 0; nq < 4; nq++) {
                MMA(d[ms][2*nq],   Ah[ms], Bh[nq][0], Bh[nq][1]);
                MMA(d[ms][2*nq+1], Ah[ms], Bh[nq][2], Bh[nq][3]);
                MMA(d[ms][2*nq],   Ah[ms], Bl[nq][0], Bl[nq][1]);
                MMA(d[ms][2*nq+1], Ah[ms], Bl[nq][2], Bl[nq][3]);
                MMA(d[ms][2*nq],   Al[ms], Bh[nq][0], Bh[nq][1]);
                MMA(d[ms][2*nq+1], Al[ms], Bh[nq][2], Bh[nq][3]);
            }
    }
}
// A = P^T via trans-ldmatrix from P[r][m]; B = Q/nm via trans from [r][c]/[m][c]
__device__ __forceinline__ void gemm_tt(float d[2][8][4], uint32_t smb, int ah, int al, int bh_, int bl_,
                                        int wm, int wn, int lane) {
    const int ar = (lane & 7) + (lane >> 4) * 8, am = ((lane >> 3) & 1) * 8;
    const int br = (lane & 15), bc = (lane >> 4) * 8;
#pragma unroll
    for (int ks = 0; ks < 8; ks++) {
        int k0 = ks * 16;
        uint32_t Ah[2][4], Al[2][4], Bh[4][4], Bl[4][4];
#pragma unroll
        for (int ms = 0; ms < 2; ms++) {
            uint32_t o = smb + (uint32_t)((k0 + ar) * 272 + (wm * 32 + ms * 16 + am) * 2);
            LDM4T(Ah[ms], o + ah); LDM4T(Al[ms], o + al);
        }
#pragma unroll
        for (int nq = 0; nq < 4; nq++) {
            uint32_t o = smb + (uint32_t)((k0 + br) * 272 + (wn * 64 + nq * 16 + bc) * 2);
            LDM4T(Bh[nq], o + bh_); LDM4T(Bl[nq], o + bl_);
        }
#pragma unroll
        for (int ms = 0; ms < 2; ms++)
#pragma unroll
            for (int nq = 0; nq < 4; nq++) {
                MMA(d[ms][2*nq],   Ah[ms], Bh[nq][0], Bh[nq][1]);
                MMA(d[ms][2*nq+1], Ah[ms], Bh[nq][2], Bh[nq][3]);
                MMA(d[ms][2*nq],   Ah[ms], Bl[nq][0], Bl[nq][1]);
                MMA(d[ms][2*nq+1], Ah[ms], Bl[nq][2], Bl[nq][3]);
                MMA(d[ms][2*nq],   Al[ms], Bh[nq][0], Bh[nq][1]);
                MMA(d[ms][2*nq+1], Al[ms], Bh[nq][2], Bh[nq][3]);
            }
    }
}
// mixed: A non-trans (P[r][m] for attn@nm), B trans (nm[m][c])
__device__ __forceinline__ void gemm_nt(float d[2][8][4], uint32_t smb, int ah, int al, int bh_, int bl_,
                                        int wm, int wn, int lane) {
    const int ar = (lane & 15), ak = (lane >> 4) * 8;
    const int br = (lane & 15), bc = (lane >> 4) * 8;
#pragma unroll
    for (int ks = 0; ks < 8; ks++) {
        int k0 = ks * 16;
        uint32_t Ah[2][4], Al[2][4], Bh[4][4], Bl[4][4];
#pragma unroll
        for (int ms = 0; ms < 2; ms++) {
            uint32_t o = smb + (uint32_t)((wm * 32 + ms * 16 + ar) * 272 + (k0 + ak) * 2);
            LDM4(Ah[ms], o + ah); LDM4(Al[ms], o + al);
        }
#pragma unroll
        for (int nq = 0; nq < 4; nq++) {
            uint32_t o = smb + (uint32_t)((k0 + br) * 272 + (wn * 64 + nq * 16 + bc) * 2);
            LDM4T(Bh[nq], o + bh_); LDM4T(Bl[nq], o + bl_);
        }
#pragma unroll
        for (int ms = 0; ms < 2; ms++)
#pragma unroll
            for (int nq = 0; nq < 4; nq++) {
                MMA(d[ms][2*nq],   Ah[ms], Bh[nq][0], Bh[nq][1]);
                MMA(d[ms][2*nq+1], Ah[ms], Bh[nq][2], Bh[nq][3]);
                MMA(d[ms][2*nq],   Ah[ms], Bl[nq][0], Bl[nq][1]);
                MMA(d[ms][2*nq+1], Ah[ms], Bl[nq][2], Bl[nq][3]);
                MMA(d[ms][2*nq],   Al[ms], Bh[nq][0], Bh[nq][1]);
                MMA(d[ms][2*nq+1], Al[ms], Bh[nq][2], Bh[nq][3]);
            }
    }
}

// write S fragments to smem fp32 [r][SS]
__device__ __forceinline__ void frag2s(float d[2][8][4], char* sm, int wm, int wn, int lane) {
    float* S = (float*)(sm + SOFF);
#pragma unroll
    for (int ms = 0; ms < 2; ms++)
#pragma unroll
        for (int nt = 0; nt < 8; nt++) {
            int r = wm * 32 + ms * 16 + (lane >> 2);
            int c = wn * 64 + nt * 8 + (lane & 3) * 2;
            S[r * SS + c] = d[ms][nt][0]; S[r * SS + c + 1] = d[ms][nt][1];
            S[(r + 8) * SS + c] = d[ms][nt][2]; S[(r + 8) * SS + c + 1] = d[ms][nt][3];
        }
}

__global__ void zero_kernel() {
    int i = blockIdx.x * blockDim.x + threadIdx.x;
    if (i < MD * CD) g_add_mem[i] = 0.0f;
}

__global__ void __launch_bounds__(256, 1)
phase1_kernel(const float* __restrict__ q, const float* __restrict__ mem) {
    extern __shared__ char sm[];
    const uint32_t smb = smem_u32(sm);
    const int tid = threadIdx.x, lane = tid & 31, w = tid >> 5;
    const int wm = w >> 1, wn = w & 1;
    const int row0 = blockIdx.x * 128;

    float d[2][8][4];
#pragma unroll
    for (int a = 0; a < 2; a++)
#pragma unroll
        for (int b = 0; b < 8; b++)
#pragma unroll
            for (int c = 0; c < 4; c++) d[a][b][c] = 0.0f;
    // S = Q @ mem^T over 2 k-chunks
    for (int kc = 0; kc < 2; kc++) {
        ldf(q + (size_t)row0 * CD + kc * 128, sm, QH, QL, tid, 0);
        ldf(mem + kc * 128, sm, MH, ML, tid, 0);
        __syncthreads();
        gemm_nn(d, smb, QH, QL, MH, ML, wm, wn, lane);
        __syncthreads();
    }
    frag2s(d, sm, wm, wn, lane);
    __syncthreads();
    // softmax: thread pair (2r, 2r+1) handles row r halves
    {
        float* S = (float*)(sm + SOFF);
        const int r = tid >> 1, hf = tid & 1;
        float v[64], mx = -1e30f;
#pragma unroll
        for (int j = 0; j < 64; j++) { v[j] = S[r * SS + hf * 64 + j]; mx = fmaxf(mx, v[j]); }
        mx = fmaxf(mx, __shfl_xor_sync(0xffffffffu, mx, 1));
        float sum = 0.0f;
#pragma unroll
        for (int j = 0; j < 64; j++) { v[j] = __expf(v[j] - mx); sum += v[j]; }
        sum += __shfl_xor_sync(0xffffffffu, sum, 1);
        float inv = 1.0f / sum;
        __syncthreads();  // S reads done before P overwrites? (P region separate) -- keeps order w/ ldmatrix later
#pragma unroll
        for (int j = 0; j < 64; j += 2) {
            float p0 = fmaxf(v[j] * inv, 1e-8f), p1 = fmaxf(v[j + 1] * inv, 1e-8f);
            __nv_bfloat16 h0 = __float2bfloat16(p0), h1 = __float2bfloat16(p1);
            uint32_t o = r * 272 + (hf * 64 + j) * 2;
            *(uint32_t*)(sm + PH + o) = pk(h0, h1);
            *(uint32_t*)(sm + PL + o) = pk(__float2bfloat16(p0 - __bfloat162float(h0)),
                                           __float2bfloat16(p1 - __bfloat162float(h1)));
        }
    }
    __syncthreads();
    // add_mem[m][c] += P^T @ Q : c in 2 chunks, A=P^T (trans), B=Q (trans)
    for (int cc = 0; cc < 2; cc++) {
        ldf(q + (size_t)row0 * CD + cc * 128, sm, QH, QL, tid, 0);
#pragma unroll
        for (int a = 0; a < 2; a++)
#pragma unroll
            for (int b = 0; b < 8; b++)
#pragma unroll
                for (int c = 0; c < 4; c++) d[a][b][c] = 0.0f;
        __syncthreads();
        gemm_tt(d, smb, PH, PL, QH, QL, wm, wn, lane);
#pragma unroll
        for (int ms = 0; ms < 2; ms++)
#pragma unroll
            for (int nt = 0; nt < 8; nt++) {
                int m = wm * 32 + ms * 16 + (lane >> 2);
                int c = cc * 128 + wn * 64 + nt * 8 + (lane & 3) * 2;
                atomicAdd(&g_add_mem[m * CD + c], d[ms][nt][0]);
                atomicAdd(&g_add_mem[m * CD + c + 1], d[ms][nt][1]);
                atomicAdd(&g_add_mem[(m + 8) * CD + c], d[ms][nt][2]);
                atomicAdd(&g_add_mem[(m + 8) * CD + c + 1], d[ms][nt][3]);
            }
        __syncthreads();
    }
}

__global__ void __launch_bounds__(256)
gate_kernel(const float* __restrict__ mem, const float* __restrict__ U_w, const float* __restrict__ U_b,
            const float* __restrict__ W_w, const float* __restrict__ W_b, float* __restrict__ out_nm) {
    __shared__ float mrow[CD], arow[CD], red[256];
    const int m = blockIdx.x, c = threadIdx.x;
    mrow[c] = mem[(size_t)m * CD + c];
    arow[c] = g_add_mem[(size_t)m * CD + c];
    __syncthreads();
    float acc = U_b[c] + W_b[c];
    const float* uw = U_w + (size_t)c * CD;
    const float* ww = W_w + (size_t)c * CD;
#pragma unroll 8
    for (int k = 0; k < CD; k++) acc = fmaf(mrow[k], uw[k], fmaf(arow[k], ww[k], acc));
    float g = 1.0f / (1.0f + __expf(-acc));
    float nm = 0.9f * mrow[c] + 0.1f * ((1.0f - g) * mrow[c] + g * arow[c]);
    red[c] = nm * nm; __syncthreads();
    for (int s = 128; s > 0; s >>= 1) { if (c < s) red[c] += red[c + s]; __syncthreads(); }
    float v = nm / fmaxf(sqrtf(red[0]), 1e-12f);
    out_nm[(size_t)m * CD + c] = v;
    __nv_bfloat16 h = __float2bfloat16(v);
    g_nm_h[(size_t)m * CD + c] = h;
    g_nm_l[(size_t)m * CD + c] = __float2bfloat16(v - __bfloat162float(h));
}

__global__ void __launch_bounds__(256, 1)
phase2_kernel(const float* __restrict__ q, float* __restrict__ out, float* __restrict__ attn_out) {
    extern __shared__ char sm[];
    const uint32_t smb = smem_u32(sm);
    const int tid = threadIdx.x, lane = tid & 31, w = tid >> 5;
    const int wm = w >> 1, wn = w & 1;
    const int row0 = blockIdx.x * 128;

    float d[2][8][4];
#pragma unroll
    for (int a = 0; a < 2; a++)
#pragma unroll
        for (int b = 0; b < 8; b++)
#pragma unroll
            for (int c = 0; c < 4; c++) d[a][b][c] = 0.0f;
    // S = Q @ nm^T  (+ q copy into out[:, :256])
    for (int kc = 0; kc < 2; kc++) {
        ldf(q + (size_t)row0 * CD + kc * 128, sm, QH, QL, tid,
            out + (size_t)row0 * 512 + kc * 128);
        ldb(g_nm_h + kc * 128, g_nm_l + kc * 128, sm, MH, ML, tid);
        __syncthreads();
        gemm_nn(d, smb, QH, QL, MH, ML, wm, wn, lane);
        __syncthreads();
    }
    frag2s(d, sm, wm, wn, lane);
    __syncthreads();
    // softmax -> shrink -> L1 norm; P hi/lo to smem
    {
        float* S = (float*)(sm + SOFF);
        const int r = tid >> 1, hf = tid & 1;
        float v[64], mx = -1e30f;
#pragma unroll
        for (int j = 0; j < 64; j++) { v[j] = S[r * SS + hf * 64 + j]; mx = fmaxf(mx, v[j]); }
        mx = fmaxf(mx, __shfl_xor_sync(0xffffffffu, mx, 1));
        float sum = 0.0f;
#pragma unroll
        for (int j = 0; j < 64; j++) { v[j] = __expf(v[j] - mx); sum += v[j]; }
        sum += __shfl_xor_sync(0xffffffffu, sum, 1);
        float inv = 1.0f / sum, l1 = 0.0f;
#pragma unroll
        for (int j = 0; j < 64; j++) {
            float a = v[j] * inv, dd = a - 0.0025f;
            float a2 = fmaxf(dd, 0.0f) * a / (fabsf(dd) + 1e-12f);
            v[j] = a2; l1 += a2;
        }
        l1 += __shfl_xor_sync(0xffffffffu, l1, 1);
        float invl = 1.0f / fmaxf(l1, 1e-12f);
#pragma unroll
        for (int j = 0; j < 64; j += 2) {
            float p0 = v[j] * invl, p1 = v[j + 1] * invl;
            __nv_bfloat16 h0 = __float2bfloat16(p0), h1 = __float2bfloat16(p1);
            uint32_t o = r * 272 + (hf * 64 + j) * 2;
            *(uint32_t*)(sm + PH + o) = pk(h0, h1);
            *(uint32_t*)(sm + PL + o) = pk(__float2bfloat16(p0 - __bfloat162float(h0)),
                                           __float2bfloat16(p1 - __bfloat162float(h1)));
        }
    }
    __syncthreads();
    // attn out (fp32 = hi + lo), coalesced
#pragma unroll
    for (int i = 0; i < 16; i++) {
        int e = tid + i * 256, r = e >> 5, m4 = e & 31;
        uint32_t o = r * 272 + m4 * 8;
        uint2 hh = *(uint2*)(sm + PH + o), ll = *(uint2*)(sm + PL + o);
        *(float4*)(attn_out + (size_t)(row0 + r) * MD + m4 * 4) =
            make_float4(bl(hh.x) + bl(ll.x), bh(hh.x) + bh(ll.x),
                        bl(hh.y) + bl(ll.y), bh(hh.y) + bh(ll.y));
    }
    // add_memory = P @ nm : c in 2 chunks; A=P non-trans, B=nm trans
    for (int cc = 0; cc < 2; cc++) {
        ldb(g_nm_h + cc * 128, g_nm_l + cc * 128, sm, QH, QL, tid);  // nm tile at region 0 (S dead)
#pragma unroll
        for (int a = 0; a < 2; a++)
#pragma unroll
            for (int b = 0; b < 8; b++)
#pragma unroll
                for (int c = 0; c < 4; c++) d[a][b][c] = 0.0f;
        __syncthreads();
        gemm_nt(d, smb, PH, PL, QH, QL, wm, wn, lane);
        // bounce for coalesced stores
        float* B = (float*)(sm + BOUNCE);
#pragma unroll
        for (int ms = 0; ms < 2; ms++)
#pragma unroll
            for (int nt = 0; nt < 8; nt++) {
                int r = wm * 32 + ms * 16 + (lane >> 2);
                int c = wn * 64 + nt * 8 + (lane & 3) * 2;
                B[r * 132 + c] = d[ms][nt][0]; B[r * 132 + c + 1] = d[ms][nt][1];
                B[(r + 8) * 132 + c] = d[ms][nt][2]; B[(r + 8) * 132 + c + 1] = d[ms][nt][3];
            }
        __syncthreads();
#pragma unroll
        for (int i = 0; i < 16; i++) {
            int e = tid + i * 256, r = e >> 5, c4 = e & 31;
            *(float4*)(out + (size_t)(row0 + r) * 512 + 256 + cc * 128 + c4 * 4) =
                *(float4*)(B + r * 132 + c4 * 4);
        }
        __syncthreads();
    }
}

extern "C" void kernel_launch(void* const* d_in, const int* in_sizes, int n_in,
                              void* d_out, int out_size) {
    const float* q = (const float*)d_in[0];
    const float* mem = (const float*)d_in[1];
    float* out = (float*)d_out;
    cudaFuncSetAttribute(phase1_kernel, cudaFuncAttributeMaxDynamicSharedMemorySize, SMEMB);
    cudaFuncSetAttribute(phase2_kernel, cudaFuncAttributeMaxDynamicSharedMemorySize, SMEMB);
    zero_kernel<<<(MD * CD + 255) / 256, 256>>>();
    phase1_kernel<<<NB, 256, SMEMB>>>(q, mem);
    gate_kernel<<<MD, 256>>>(mem, (const float*)d_in[2], (const float*)d_in[3],
                             (const float*)d_in[4], (const float*)d_in[5], out + NM_OFF);
    phase2_kernel<<<NB, 256, SMEMB>>>(q, out, out + ATTN_OFF);
}

// round 6
// speedup vs baseline: 2.0672x; 1.1405x over previous
#include <cuda_runtime.h>
#include <cuda_bf16.h>
#include <cstdint>

#define TT 131072
#define CD 256
#define MD 128
#define NB 1024
#define ATTN_OFF ((size_t)TT*2*CD)
#define NM_OFF (ATTN_OFF+(size_t)TT*MD)

// smem regions (bytes). K-chunk tiles: 128 rows x 64 bf16, row stride 144B.
#define QH 0
#define QL 18432
#define MH 36864
#define ML 55296
// P tiles: 128 x 128 bf16, row stride 272B
#define PH 73728
#define PL 108544
#define SMX 143360
#define SSUM 145408
#define SMEMB 147456

__device__ float g_add_mem[MD*CD];
__device__ __nv_bfloat16 g_nm_h[MD*CD], g_nm_l[MD*CD];

__device__ __forceinline__ uint32_t smem_u32(const void* p) {
    uint32_t a;
    asm("{ .reg .u64 t; cvta.to.shared.u64 t, %1; cvt.u32.u64 %0, t; }" : "=r"(a) : "l"(p));
    return a;
}
#define LDM4(r, a) asm volatile("ldmatrix.sync.aligned.m8n8.x4.shared.b16 {%0,%1,%2,%3}, [%4];" \
    : "=r"((r)[0]),"=r"((r)[1]),"=r"((r)[2]),"=r"((r)[3]) : "r"(a))
#define LDM4T(r, a) asm volatile("ldmatrix.sync.aligned.m8n8.x4.trans.shared.b16 {%0,%1,%2,%3}, [%4];" \
    : "=r"((r)[0]),"=r"((r)[1]),"=r"((r)[2]),"=r"((r)[3]) : "r"(a))
#define MMA(d, a, b0, b1) asm volatile( \
    "mma.sync.aligned.m16n8k16.row.col.f32.bf16.bf16.f32 {%0,%1,%2,%3}, {%4,%5,%6,%7}, {%8,%9}, {%0,%1,%2,%3};" \
    : "+f"((d)[0]),"+f"((d)[1]),"+f"((d)[2]),"+f"((d)[3]) \
    : "r"((a)[0]),"r"((a)[1]),"r"((a)[2]),"r"((a)[3]), "r"(b0),"r"(b1))

__device__ __forceinline__ uint32_t pk(__nv_bfloat16 a, __nv_bfloat16 b) {
    return (uint32_t)__bfloat16_as_ushort(a) | ((uint32_t)__bfloat16_as_ushort(b) << 16);
}
__device__ __forceinline__ float bl(uint32_t u) { return __bfloat162float(__ushort_as_bfloat16((unsigned short)u)); }
__device__ __forceinline__ float bh(uint32_t u) { return __bfloat162float(__ushort_as_bfloat16((unsigned short)(u >> 16))); }

// ---- chunk loaders: 128 rows x 64 cols, 512 threads, 4 float4/thread ----
__device__ __forceinline__ void ldreg_f(const float* __restrict__ src, float4* v, int tid) {
#pragma unroll
    for (int i = 0; i < 4; i++) {
        int e = tid + i * 512;
        v[i] = *(const float4*)(src + (size_t)(e >> 4) * CD + (e & 15) * 4);
    }
}
__device__ __forceinline__ void sts_f(char* sm, int dh, int dl, const float4* v, int tid, float* ocopy) {
#pragma unroll
    for (int i = 0; i < 4; i++) {
        int e = tid + i * 512, r = e >> 4, c4 = e & 15;
        float4 x = v[i];
        if (ocopy) *(float4*)(ocopy + (size_t)r * 512 + c4 * 4) = x;
        __nv_bfloat16 h0 = __float2bfloat16(x.x), h1 = __float2bfloat16(x.y);
        __nv_bfloat16 h2 = __float2bfloat16(x.z), h3 = __float2bfloat16(x.w);
        uint32_t o = r * 144 + c4 * 8;
        *(uint2*)(sm + dh + o) = make_uint2(pk(h0, h1), pk(h2, h3));
        *(uint2*)(sm + dl + o) = make_uint2(
            pk(__float2bfloat16(x.x - __bfloat162float(h0)), __float2bfloat16(x.y - __bfloat162float(h1))),
            pk(__float2bfloat16(x.z - __bfloat162float(h2)), __float2bfloat16(x.w - __bfloat162float(h3))));
    }
}
__device__ __forceinline__ void ldreg_b(const __nv_bfloat16* __restrict__ sh, const __nv_bfloat16* __restrict__ sl,
                                        uint2* vh, uint2* vl, int tid) {
#pragma unroll
    for (int i = 0; i < 4; i++) {
        int e = tid + i * 512, r = e >> 4, c4 = e & 15;
        vh[i] = *(const uint2*)(sh + (size_t)r * CD + c4 * 4);
        vl[i] = *(const uint2*)(sl + (size_t)r * CD + c4 * 4);
    }
}
__device__ __forceinline__ void sts_b(char* sm, int dh, int dl, const uint2* vh, const uint2* vl, int tid) {
#pragma unroll
    for (int i = 0; i < 4; i++) {
        int e = tid + i * 512, r = e >> 4, c4 = e & 15;
        uint32_t o = r * 144 + c4 * 8;
        *(uint2*)(sm + dh + o) = vh[i];
        *(uint2*)(sm + dl + o) = vl[i];
    }
}

// ---- S GEMM piece: d[2][4][4] += A(QH/QL)[32 rows] x B(MH/ML)^T[32 cols], K=64 ----
__device__ __forceinline__ void gemm64_nn(float d[2][4][4], uint32_t smb, int wm, int wn, int lane) {
    const int ar = lane & 15, ak = (lane >> 4) * 8;
    const int br = (lane & 7) + ((lane >> 4) & 1) * 8, bk = ((lane >> 3) & 1) * 8;
#pragma unroll
    for (int ks = 0; ks < 4; ks++) {
        int k0 = ks * 16;
        uint32_t Ah[2][4], Al[2][4], Bh[2][4], Bl[2][4];
#pragma unroll
        for (int ms = 0; ms < 2; ms++) {
            uint32_t o = smb + (uint32_t)((wm * 32 + ms * 16 + ar) * 144 + (k0 + ak) * 2);
            LDM4(Ah[ms], o + QH); LDM4(Al[ms], o + QL);
        }
#pragma unroll
        for (int nq = 0; nq < 2; nq++) {
            uint32_t o = smb + (uint32_t)((wn * 32 + nq * 16 + br) * 144 + (k0 + bk) * 2);
            LDM4(Bh[nq], o + MH); LDM4(Bl[nq], o + ML);
        }
#pragma unroll
        for (int ms = 0; ms < 2; ms++)
#pragma unroll
            for (int nq = 0; nq < 2; nq++) {
                MMA(d[ms][2*nq],   Ah[ms], Bh[nq][0], Bh[nq][1]);
                MMA(d[ms][2*nq+1], Ah[ms], Bh[nq][2], Bh[nq][3]);
                MMA(d[ms][2*nq],   Ah[ms], Bl[nq][0], Bl[nq][1]);
                MMA(d[ms][2*nq+1], Ah[ms], Bl[nq][2], Bl[nq][3]);
                MMA(d[ms][2*nq],   Al[ms], Bh[nq][0], Bh[nq][1]);
                MMA(d[ms][2*nq+1], Al[ms], Bh[nq][2], Bh[nq][3]);
            }
    }
}
// ---- phase1 D: d[2][2][4] += P^T(trans, PH/PL) x Q(trans, QH/QL), K=128, 16 cols ----
__device__ __forceinline__ void gemm_tt2(float d[2][2][4], uint32_t smb, int wm, int wn, int lane) {
    const int ar = (lane & 7) + (lane >> 4) * 8, am = ((lane >> 3) & 1) * 8;
    const int br = lane & 15, bc = (lane >> 4) * 8;
#pragma unroll
    for (int ks = 0; ks < 8; ks++) {
        int k0 = ks * 16;
        uint32_t Ah[2][4], Al[2][4], Bh[4], Bl[4];
#pragma unroll
        for (int ms = 0; ms < 2; ms++) {
            uint32_t o = smb + (uint32_t)((k0 + ar) * 272 + (wm * 32 + ms * 16 + am) * 2);
            LDM4T(Ah[ms], o + PH); LDM4T(Al[ms], o + PL);
        }
        {
            uint32_t o = smb + (uint32_t)((k0 + br) * 144 + (wn * 16 + bc) * 2);
            LDM4T(Bh, o + QH); LDM4T(Bl, o + QL);
        }
#pragma unroll
        for (int ms = 0; ms < 2; ms++) {
            MMA(d[ms][0], Ah[ms], Bh[0], Bh[1]);
            MMA(d[ms][1], Ah[ms], Bh[2], Bh[3]);
            MMA(d[ms][0], Ah[ms], Bl[0], Bl[1]);
            MMA(d[ms][1], Ah[ms], Bl[2], Bl[3]);
            MMA(d[ms][0], Al[ms], Bh[0], Bh[1]);
            MMA(d[ms][1], Al[ms], Bh[2], Bh[3]);
        }
    }
}
// ---- phase2 D: d[2][2][4] += P(non-trans, PH/PL) x nm^T(trans, MH/ML), K=128 ----
__device__ __forceinline__ void gemm_nt2(float d[2][2][4], uint32_t smb, int wm, int wn, int lane) {
    const int ar = lane & 15, ak = (lane >> 4) * 8;
    const int br = lane & 15, bc = (lane >> 4) * 8;
#pragma unroll
    for (int ks = 0; ks < 8; ks++) {
        int k0 = ks * 16;
        uint32_t Ah[2][4], Al[2][4], Bh[4], Bl[4];
#pragma unroll
        for (int ms = 0; ms < 2; ms++) {
            uint32_t o = smb + (uint32_t)((wm * 32 + ms * 16 + ar) * 272 + (k0 + ak) * 2);
            LDM4(Ah[ms], o + PH); LDM4(Al[ms], o + PL);
        }
        {
            uint32_t o = smb + (uint32_t)((k0 + br) * 144 + (wn * 16 + bc) * 2);
            LDM4T(Bh, o + MH); LDM4T(Bl, o + ML);
        }
#pragma unroll
        for (int ms = 0; ms < 2; ms++) {
            MMA(d[ms][0], Ah[ms], Bh[0], Bh[1]);
            MMA(d[ms][1], Ah[ms], Bh[2], Bh[3]);
            MMA(d[ms][0], Ah[ms], Bl[0], Bl[1]);
            MMA(d[ms][1], Ah[ms], Bl[2], Bl[3]);
            MMA(d[ms][0], Al[ms], Bh[0], Bh[1]);
            MMA(d[ms][1], Al[ms], Bh[2], Bh[3]);
        }
    }
}

__global__ void zero_kernel() {
    int i = blockIdx.x * blockDim.x + threadIdx.x;
    if (i < MD * CD) g_add_mem[i] = 0.0f;
}

__global__ void __launch_bounds__(512, 1)
phase1_kernel(const float* __restrict__ q, const float* __restrict__ mem) {
    extern __shared__ char sm[];
    const uint32_t smb = smem_u32(sm);
    const int tid = threadIdx.x, lane = tid & 31, w = tid >> 5;
    const int wm = w >> 2, wn = w & 3, lr = lane >> 2, lq = lane & 3;
    const int row0 = blockIdx.x * 128;
    float* smx = (float*)(sm + SMX);
    float* ssu = (float*)(sm + SSUM);

    float d[2][4][4];
#pragma unroll
    for (int a = 0; a < 2; a++)
#pragma unroll
        for (int b = 0; b < 4; b++)
#pragma unroll
            for (int c = 0; c < 4; c++) d[a][b][c] = 0.0f;

    // S = Q @ mem^T, 4 K-chunks with register prefetch
    float4 va[4], vb[4];
    ldreg_f(q + (size_t)row0 * CD, va, tid);
    ldreg_f(mem, vb, tid);
    for (int kc = 0; kc < 4; kc++) {
        sts_f(sm, QH, QL, va, tid, 0);
        sts_f(sm, MH, ML, vb, tid, 0);
        if (kc < 3) {
            ldreg_f(q + (size_t)row0 * CD + (kc + 1) * 64, va, tid);
            ldreg_f(mem + (kc + 1) * 64, vb, tid);
        }
        __syncthreads();
        gemm64_nn(d, smb, wm, wn, lane);
        __syncthreads();
    }

    // fragment softmax (rows across 4 wn warps x 4 lane quads)
    float mx2[2][2], inv2[2][2];
#pragma unroll
    for (int ms = 0; ms < 2; ms++)
#pragma unroll
        for (int rh = 0; rh < 2; rh++) {
            float m_ = -1e30f;
#pragma unroll
            for (int nt = 0; nt < 4; nt++) m_ = fmaxf(m_, fmaxf(d[ms][nt][rh*2], d[ms][nt][rh*2+1]));
            m_ = fmaxf(m_, __shfl_xor_sync(~0u, m_, 1));
            m_ = fmaxf(m_, __shfl_xor_sync(~0u, m_, 2));
            mx2[ms][rh] = m_;
            if (lq == 0) smx[(wm*32 + ms*16 + lr + rh*8) * 4 + wn] = m_;
        }
    __syncthreads();
#pragma unroll
    for (int ms = 0; ms < 2; ms++)
#pragma unroll
        for (int rh = 0; rh < 2; rh++) {
            int r = wm*32 + ms*16 + lr + rh*8;
            float m_ = fmaxf(fmaxf(smx[r*4], smx[r*4+1]), fmaxf(smx[r*4+2], smx[r*4+3]));
            float s = 0.0f;
#pragma unroll
            for (int nt = 0; nt < 4; nt++) {
                d[ms][nt][rh*2] = __expf(d[ms][nt][rh*2] - m_);
                d[ms][nt][rh*2+1] = __expf(d[ms][nt][rh*2+1] - m_);
                s += d[ms][nt][rh*2] + d[ms][nt][rh*2+1];
            }
            s += __shfl_xor_sync(~0u, s, 1);
            s += __shfl_xor_sync(~0u, s, 2);
            if (lq == 0) ssu[r*4 + wn] = s;
        }
    __syncthreads();
#pragma unroll
    for (int ms = 0; ms < 2; ms++)
#pragma unroll
        for (int rh = 0; rh < 2; rh++) {
            int r = wm*32 + ms*16 + lr + rh*8;
            inv2[ms][rh] = 1.0f / (ssu[r*4] + ssu[r*4+1] + ssu[r*4+2] + ssu[r*4+3]);
        }
    // P tiles (hi/lo), clamp 1e-8
#pragma unroll
    for (int ms = 0; ms < 2; ms++)
#pragma unroll
        for (int rh = 0; rh < 2; rh++) {
            int r = wm*32 + ms*16 + lr + rh*8;
#pragma unroll
            for (int nt = 0; nt < 4; nt++) {
                int c = wn*32 + nt*8 + lq*2;
                float p0 = fmaxf(d[ms][nt][rh*2] * inv2[ms][rh], 1e-8f);
                float p1 = fmaxf(d[ms][nt][rh*2+1] * inv2[ms][rh], 1e-8f);
                __nv_bfloat16 h0 = __float2bfloat16(p0), h1 = __float2bfloat16(p1);
                *(uint32_t*)(sm + PH + r*272 + c*2) = pk(h0, h1);
                *(uint32_t*)(sm + PL + r*272 + c*2) = pk(__float2bfloat16(p0 - __bfloat162float(h0)),
                                                         __float2bfloat16(p1 - __bfloat162float(h1)));
            }
        }
    __syncthreads();

    // add_mem += P^T @ Q (4 c-chunks, prefetch)
    ldreg_f(q + (size_t)row0 * CD, va, tid);
    for (int cc = 0; cc < 4; cc++) {
        sts_f(sm, QH, QL, va, tid, 0);
        if (cc < 3) ldreg_f(q + (size_t)row0 * CD + (cc + 1) * 64, va, tid);
        __syncthreads();
        float d2[2][2][4];
#pragma unroll
        for (int a = 0; a < 2; a++)
#pragma unroll
            for (int b = 0; b < 2; b++)
#pragma unroll
                for (int c = 0; c < 4; c++) d2[a][b][c] = 0.0f;
        gemm_tt2(d2, smb, wm, wn, lane);
#pragma unroll
        for (int ms = 0; ms < 2; ms++)
#pragma unroll
            for (int nh = 0; nh < 2; nh++) {
                int m = wm*32 + ms*16 + lr;
                int c = cc*64 + wn*16 + nh*8 + lq*2;
                atomicAdd(&g_add_mem[m*CD + c], d2[ms][nh][0]);
                atomicAdd(&g_add_mem[m*CD + c + 1], d2[ms][nh][1]);
                atomicAdd(&g_add_mem[(m+8)*CD + c], d2[ms][nh][2]);
                atomicAdd(&g_add_mem[(m+8)*CD + c + 1], d2[ms][nh][3]);
            }
        __syncthreads();
    }
}

__global__ void __launch_bounds__(256)
gate_kernel(const float* __restrict__ mem, const float* __restrict__ U_w, const float* __restrict__ U_b,
            const float* __restrict__ W_w, const float* __restrict__ W_b, float* __restrict__ out_nm) {
    __shared__ float mrow[CD], arow[CD], red[256];
    const int m = blockIdx.x, c = threadIdx.x;
    mrow[c] = mem[(size_t)m * CD + c];
    arow[c] = g_add_mem[(size_t)m * CD + c];
    __syncthreads();
    float acc = U_b[c] + W_b[c];
    const float* uw = U_w + (size_t)c * CD;
    const float* ww = W_w + (size_t)c * CD;
#pragma unroll 8
    for (int k = 0; k < CD; k++) acc = fmaf(mrow[k], uw[k], fmaf(arow[k], ww[k], acc));
    float g = 1.0f / (1.0f + __expf(-acc));
    float nm = 0.9f * mrow[c] + 0.1f * ((1.0f - g) * mrow[c] + g * arow[c]);
    red[c] = nm * nm; __syncthreads();
    for (int s = 128; s > 0; s >>= 1) { if (c < s) red[c] += red[c + s]; __syncthreads(); }
    float v = nm / fmaxf(sqrtf(red[0]), 1e-12f);
    out_nm[(size_t)m * CD + c] = v;
    __nv_bfloat16 h = __float2bfloat16(v);
    g_nm_h[(size_t)m * CD + c] = h;
    g_nm_l[(size_t)m * CD + c] = __float2bfloat16(v - __bfloat162float(h));
}

__global__ void __launch_bounds__(512, 1)
phase2_kernel(const float* __restrict__ q, float* __restrict__ out, float* __restrict__ attn_out) {
    extern __shared__ char sm[];
    const uint32_t smb = smem_u32(sm);
    const int tid = threadIdx.x, lane = tid & 31, w = tid >> 5;
    const int wm = w >> 2, wn = w & 3, lr = lane >> 2, lq = lane & 3;
    const int row0 = blockIdx.x * 128;
    float* smx = (float*)(sm + SMX);
    float* ssu = (float*)(sm + SSUM);

    float d[2][4][4];
#pragma unroll
    for (int a = 0; a < 2; a++)
#pragma unroll
        for (int b = 0; b < 4; b++)
#pragma unroll
            for (int c = 0; c < 4; c++) d[a][b][c] = 0.0f;

    // S = Q @ nm^T (+ q copy)
    float4 va[4];
    uint2 nh_[4], nl_[4];
    ldreg_f(q + (size_t)row0 * CD, va, tid);
    ldreg_b(g_nm_h, g_nm_l, nh_, nl_, tid);
    for (int kc = 0; kc < 4; kc++) {
        sts_f(sm, QH, QL, va, tid, out + (size_t)row0 * 512 + kc * 64);
        sts_b(sm, MH, ML, nh_, nl_, tid);
        if (kc < 3) {
            ldreg_f(q + (size_t)row0 * CD + (kc + 1) * 64, va, tid);
            ldreg_b(g_nm_h + (kc + 1) * 64, g_nm_l + (kc + 1) * 64, nh_, nl_, tid);
        }
        __syncthreads();
        gemm64_nn(d, smb, wm, wn, lane);
        __syncthreads();
    }

    // softmax -> hard-shrink -> L1 norm on fragments
    float inv2[2][2];
#pragma unroll
    for (int ms = 0; ms < 2; ms++)
#pragma unroll
        for (int rh = 0; rh < 2; rh++) {
            float m_ = -1e30f;
#pragma unroll
            for (int nt = 0; nt < 4; nt++) m_ = fmaxf(m_, fmaxf(d[ms][nt][rh*2], d[ms][nt][rh*2+1]));
            m_ = fmaxf(m_, __shfl_xor_sync(~0u, m_, 1));
            m_ = fmaxf(m_, __shfl_xor_sync(~0u, m_, 2));
            if (lq == 0) smx[(wm*32 + ms*16 + lr + rh*8) * 4 + wn] = m_;
        }
    __syncthreads();
#pragma unroll
    for (int ms = 0; ms < 2; ms++)
#pragma unroll
        for (int rh = 0; rh < 2; rh++) {
            int r = wm*32 + ms*16 + lr + rh*8;
            float m_ = fmaxf(fmaxf(smx[r*4], smx[r*4+1]), fmaxf(smx[r*4+2], smx[r*4+3]));
            float s = 0.0f;
#pragma unroll
            for (int nt = 0; nt < 4; nt++) {
                d[ms][nt][rh*2] = __expf(d[ms][nt][rh*2] - m_);
                d[ms][nt][rh*2+1] = __expf(d[ms][nt][rh*2+1] - m_);
                s += d[ms][nt][rh*2] + d[ms][nt][rh*2+1];
            }
            s += __shfl_xor_sync(~0u, s, 1);
            s += __shfl_xor_sync(~0u, s, 2);
            if (lq == 0) ssu[r*4 + wn] = s;
        }
    __syncthreads();
#pragma unroll
    for (int ms = 0; ms < 2; ms++)
#pragma unroll
        for (int rh = 0; rh < 2; rh++) {
            int r = wm*32 + ms*16 + lr + rh*8;
            inv2[ms][rh] = 1.0f / (ssu[r*4] + ssu[r*4+1] + ssu[r*4+2] + ssu[r*4+3]);
        }
    __syncthreads();  // before reusing smx for L1
    // shrink + L1 partials
#pragma unroll
    for (int ms = 0; ms < 2; ms++)
#pragma unroll
        for (int rh = 0; rh < 2; rh++) {
            int r = wm*32 + ms*16 + lr + rh*8;
            float l1 = 0.0f;
#pragma unroll
            for (int nt = 0; nt < 4; nt++) {
#pragma unroll
                for (int cb = 0; cb < 2; cb++) {
                    float a = d[ms][nt][rh*2+cb] * inv2[ms][rh];
                    float dd = a - 0.0025f;
                    float a2 = fmaxf(dd, 0.0f) * a / (fabsf(dd) + 1e-12f);
                    d[ms][nt][rh*2+cb] = a2; l1 += a2;
                }
            }
            l1 += __shfl_xor_sync(~0u, l1, 1);
            l1 += __shfl_xor_sync(~0u, l1, 2);
            if (lq == 0) smx[r*4 + wn] = l1;
        }
    __syncthreads();
#pragma unroll
    for (int ms = 0; ms < 2; ms++)
#pragma unroll
        for (int rh = 0; rh < 2; rh++) {
            int r = wm*32 + ms*16 + lr + rh*8;
            float invl = 1.0f / fmaxf(smx[r*4] + smx[r*4+1] + smx[r*4+2] + smx[r*4+3], 1e-12f);
#pragma unroll
            for (int nt = 0; nt < 4; nt++) {
                int c = wn*32 + nt*8 + lq*2;
                float p0 = d[ms][nt][rh*2] * invl, p1 = d[ms][nt][rh*2+1] * invl;
                __nv_bfloat16 h0 = __float2bfloat16(p0), h1 = __float2bfloat16(p1);
                *(uint32_t*)(sm + PH + r*272 + c*2) = pk(h0, h1);
                *(uint32_t*)(sm + PL + r*272 + c*2) = pk(__float2bfloat16(p0 - __bfloat162float(h0)),
                                                         __float2bfloat16(p1 - __bfloat162float(h1)));
            }
        }
    __syncthreads();
    // attn out (hi+lo reconstruct, coalesced)
#pragma unroll
    for (int i = 0; i < 8; i++) {
        int e = tid + i * 512, r = e >> 5, m4 = e & 31;
        uint32_t o = r * 272 + m4 * 8;
        uint2 hh = *(uint2*)(sm + PH + o), ll = *(uint2*)(sm + PL + o);
        *(float4*)(attn_out + (size_t)(row0 + r) * MD + m4 * 4) =
            make_float4(bl(hh.x) + bl(ll.x), bh(hh.x) + bh(ll.x),
                        bl(hh.y) + bl(ll.y), bh(hh.y) + bh(ll.y));
    }

    // add_memory = P @ nm (4 c-chunks)
    ldreg_b(g_nm_h, g_nm_l, nh_, nl_, tid);
    for (int cc = 0; cc < 4; cc++) {
        sts_b(sm, MH, ML, nh_, nl_, tid);
        if (cc < 3) ldreg_b(g_nm_h + (cc + 1) * 64, g_nm_l + (cc + 1) * 64, nh_, nl_, tid);
        __syncthreads();
        float d2[2][2][4];
#pragma unroll
        for (int a = 0; a < 2; a++)
#pragma unroll
            for (int b = 0; b < 2; b++)
#pragma unroll
                for (int c = 0; c < 4; c++) d2[a][b][c] = 0.0f;
        gemm_nt2(d2, smb, wm, wn, lane);
#pragma unroll
        for (int ms = 0; ms < 2; ms++)
#pragma unroll
            for (int nh2 = 0; nh2 < 2; nh2++) {
                int r = row0 + wm*32 + ms*16 + lr;
                int c = cc*64 + wn*16 + nh2*8 + lq*2;
                *(float2*)(out + (size_t)r * 512 + 256 + c) = make_float2(d2[ms][nh2][0], d2[ms][nh2][1]);
                *(float2*)(out + (size_t)(r + 8) * 512 + 256 + c) = make_float2(d2[ms][nh2][2], d2[ms][nh2][3]);
            }
        __syncthreads();
    }
}

extern "C" void kernel_launch(void* const* d_in, const int* in_sizes, int n_in,
                              void* d_out, int out_size) {
    const float* q = (const float*)d_in[0];
    const float* mem = (const float*)d_in[1];
    float* out = (float*)d_out;
    cudaFuncSetAttribute(phase1_kernel, cudaFuncAttributeMaxDynamicSharedMemorySize, SMEMB);
    cudaFuncSetAttribute(phase2_kernel, cudaFuncAttributeMaxDynamicSharedMemorySize, SMEMB);
    zero_kernel<<<(MD * CD + 255) / 256, 256>>>();
    phase1_kernel<<<NB, 512, SMEMB>>>(q, mem);
    gate_kernel<<<MD, 256>>>(mem, (const float*)d_in[2], (const float*)d_in[3],
                             (const float*)d_in[4], (const float*)d_in[5], out + NM_OFF);
    phase2_kernel<<<NB, 512, SMEMB>>>(q, out, out + ATTN_OFF);
}